// round 3
// baseline (speedup 1.0000x reference)
#include <cuda_runtime.h>
#include <cstdint>

// OcrEmbedding: out[b,t,:] = sum_{s=0..3, id!=0} table[id[b,t,s], :]
// B=32, T=512, S=4, D=256, V=50000.
// d_in[0] = subtoken_ids (int32, B*T*S), d_in[1] = table (float32, V*D)
// Output: float32, B*T*D.
//
// Strategy: cp.async (LDGSTS) gather into SMEM to escape the per-SM LDG
// outstanding-request cap. Each CTA handles R=8 token rows:
//   stage 1: 8 rows x 4 ids x 1KB gathered via 16B cp.async.cg (zero-fill
//            when id==0 using src-size=0), all independent -> huge MLP.
//   stage 2: sum 4 smem rows per output chunk, STG.128 out.

#define BT    (32 * 512)    // 16384 token rows
#define D4    64            // float4 chunks per row
#define R     8             // rows per CTA
#define THREADS 256

__device__ __forceinline__ uint32_t smem_u32(const void* p) {
    uint32_t a;
    asm("{ .reg .u64 t; cvta.to.shared.u64 t, %1; cvt.u32.u64 %0, t; }"
        : "=r"(a) : "l"(p));
    return a;
}

__global__ __launch_bounds__(THREADS) void ocr_embed_cpasync_kernel(
    const int* __restrict__ ids,          // [BT*4]
    const float4* __restrict__ table,     // [V, D4]
    float4* __restrict__ out)             // [BT, D4]
{
    extern __shared__ float4 buf[];       // [R][4][D4] = 8*4*64 float4 = 32KB

    const int tid  = threadIdx.x;
    const int row0 = blockIdx.x * R;

    // ---- Stage 1: gather via cp.async ----
    // chunk c in [0, R*4*64): r = c>>8, s = (c>>6)&3, q = c&63
    // 2048 chunks / 256 threads = 8 per thread, all independent.
    #pragma unroll
    for (int i = 0; i < 8; i++) {
        int c = tid + THREADS * i;
        int r = c >> 8;
        int s = (c >> 6) & 3;
        int q = c & 63;

        int id = __ldg(&ids[(row0 + r) * 4 + s]);   // warp-broadcast (64 thr share)

        const float4* src = table + (size_t)id * D4 + q;
        uint32_t dst = smem_u32(&buf[c]);
        uint32_t sz  = (id != 0) ? 16u : 0u;        // src-size=0 -> zero-fill
        asm volatile("cp.async.cg.shared.global [%0], [%1], 16, %2;\n"
                     :: "r"(dst), "l"(src), "r"(sz) : "memory");
    }
    asm volatile("cp.async.commit_group;\n" ::: "memory");
    asm volatile("cp.async.wait_group 0;\n" ::: "memory");
    __syncthreads();

    // ---- Stage 2: sum 4 subtoken rows per output chunk ----
    // output chunks = R*64 = 512 -> 2 per thread
    #pragma unroll
    for (int j = 0; j < 2; j++) {
        int o = tid + THREADS * j;
        int r = o >> 6;
        int q = o & 63;

        const float4* p = &buf[(r * 4) * 64 + q];
        float4 a = p[0];
        float4 b = p[64];
        float4 c4 = p[128];
        float4 d = p[192];

        float4 s;
        s.x = (a.x + b.x) + (c4.x + d.x);
        s.y = (a.y + b.y) + (c4.y + d.y);
        s.z = (a.z + b.z) + (c4.z + d.z);
        s.w = (a.w + b.w) + (c4.w + d.w);

        out[(size_t)(row0 + r) * D4 + q] = s;
    }
}

extern "C" void kernel_launch(void* const* d_in, const int* in_sizes, int n_in,
                              void* d_out, int out_size)
{
    const int*    ids   = (const int*)d_in[0];
    const float4* table = (const float4*)d_in[1];
    float4*       out   = (float4*)d_out;

    const int smem = R * 4 * D4 * sizeof(float4);   // 32 KB

    static bool attr_set = false;
    if (!attr_set) {
        cudaFuncSetAttribute(ocr_embed_cpasync_kernel,
                             cudaFuncAttributeMaxDynamicSharedMemorySize, smem);
        attr_set = true;
    }

    const int blocks = BT / R;   // 2048
    ocr_embed_cpasync_kernel<<<blocks, THREADS, smem>>>(ids, table, out);
}